// round 1
// baseline (speedup 1.0000x reference)
#include <cuda_runtime.h>
#include <float.h>

#define Bn 256
#define Ln 1026
#define Dn 1280
#define En 300
#define Hn 256
#define D4 (Dn / 4)      // 320
#define DE (Dn + En)     // 1580

// ---------------- scratch (no allocation allowed) ----------------
__device__ __align__(16) float g_pooled[Bn * Dn];
__device__ __align__(16) float g_x1[Bn * Dn];
__device__ __align__(16) float g_q[Bn * En];
__device__ __align__(16) float g_molT[En * Bn];
__device__ __align__(16) float g_attn[Bn * Bn];
__device__ __align__(16) float g_attnT[Bn * Bn];
__device__ __align__(16) float g_fx1[Bn * En];
__device__ __align__(16) float g_fx2[Bn * Dn];

// ---------------- block reductions ----------------
__device__ __forceinline__ float blockReduceMax(float v) {
    __shared__ float sh[32];
    int lane = threadIdx.x & 31;
    int wid = threadIdx.x >> 5;
#pragma unroll
    for (int o = 16; o; o >>= 1) v = fmaxf(v, __shfl_xor_sync(0xffffffffu, v, o));
    __syncthreads();
    if (lane == 0) sh[wid] = v;
    __syncthreads();
    int nw = (blockDim.x + 31) >> 5;
    if (wid == 0) {
        float x = (lane < nw) ? sh[lane] : -FLT_MAX;
#pragma unroll
        for (int o = 16; o; o >>= 1) x = fmaxf(x, __shfl_xor_sync(0xffffffffu, x, o));
        if (lane == 0) sh[0] = x;
    }
    __syncthreads();
    float r = sh[0];
    __syncthreads();
    return r;
}

__device__ __forceinline__ float blockReduceSum(float v) {
    __shared__ float sh[32];
    int lane = threadIdx.x & 31;
    int wid = threadIdx.x >> 5;
#pragma unroll
    for (int o = 16; o; o >>= 1) v += __shfl_xor_sync(0xffffffffu, v, o);
    __syncthreads();
    if (lane == 0) sh[wid] = v;
    __syncthreads();
    int nw = (blockDim.x + 31) >> 5;
    if (wid == 0) {
        float x = (lane < nw) ? sh[lane] : 0.f;
#pragma unroll
        for (int o = 16; o; o >>= 1) x += __shfl_xor_sync(0xffffffffu, x, o);
        if (lane == 0) sh[0] = x;
    }
    __syncthreads();
    float r = sh[0];
    __syncthreads();
    return r;
}

// ---------------- 1. ragged mean pool ----------------
// grid (B, 2), block 160. Each thread owns one float4 column of D.
__global__ void pool_kernel(const float* __restrict__ tok, const int* __restrict__ lens,
                            float* __restrict__ pooled) {
    int b = blockIdx.x;
    int c4 = blockIdx.y * 160 + threadIdx.x;      // 0..319
    int len = lens[b];
    int hi = len - 1;                             // rows [1, hi)
    const float4* base = (const float4*)tok + (size_t)b * (Ln * D4) + c4;
    float sx = 0.f, sy = 0.f, sz = 0.f, sw = 0.f;
    int l = 1;
    for (; l + 3 < hi; l += 4) {
        float4 v0 = base[(size_t)l * D4];
        float4 v1 = base[(size_t)(l + 1) * D4];
        float4 v2 = base[(size_t)(l + 2) * D4];
        float4 v3 = base[(size_t)(l + 3) * D4];
        sx += (v0.x + v1.x) + (v2.x + v3.x);
        sy += (v0.y + v1.y) + (v2.y + v3.y);
        sz += (v0.z + v1.z) + (v2.z + v3.z);
        sw += (v0.w + v1.w) + (v2.w + v3.w);
    }
    for (; l < hi; l++) {
        float4 v = base[(size_t)l * D4];
        sx += v.x; sy += v.y; sz += v.z; sw += v.w;
    }
    int cnt = hi - 1; if (cnt < 1) cnt = 1;
    float inv = 1.f / (float)cnt;
    float4 r = make_float4(sx * inv, sy * inv, sz * inv, sw * inv);
    ((float4*)pooled)[(size_t)b * D4 + c4] = r;
}

// ---------------- 2/3. GEMM (+bias, optional ReLU) ----------------
// C[M,N] = act(A[M,K] @ Bm[K,N] + bias), 64x64 tiles, 256 threads, 4x4/thread.
__global__ void gemm_bias_act(const float* __restrict__ A, const float* __restrict__ Bm,
                              const float* __restrict__ bias, float* __restrict__ C,
                              int M, int N, int K, int doRelu) {
    __shared__ float sA[16][64];
    __shared__ float sB[16][64];
    int tid = threadIdx.x;
    int tx = tid & 15, ty = tid >> 4;
    int row0 = blockIdx.y * 64;
    int col0 = blockIdx.x * 64;
    float c[4][4];
#pragma unroll
    for (int i = 0; i < 4; i++)
#pragma unroll
        for (int j = 0; j < 4; j++) c[i][j] = 0.f;

    for (int k0 = 0; k0 < K; k0 += 16) {
#pragma unroll
        for (int i = 0; i < 4; i++) {
            int e = tid + i * 256;
            int m = e >> 4, kk = e & 15;
            int r = row0 + m;
            sA[kk][m] = (r < M) ? A[(size_t)r * K + k0 + kk] : 0.f;
        }
#pragma unroll
        for (int i = 0; i < 4; i++) {
            int e = tid + i * 256;
            int kk = e >> 6, n = e & 63;
            int col = col0 + n;
            sB[kk][n] = (col < N) ? Bm[(size_t)(k0 + kk) * N + col] : 0.f;
        }
        __syncthreads();
#pragma unroll
        for (int kk = 0; kk < 16; kk++) {
            float4 a4 = *(const float4*)&sA[kk][ty * 4];
            float4 b4 = *(const float4*)&sB[kk][tx * 4];
            float av[4] = {a4.x, a4.y, a4.z, a4.w};
            float bv[4] = {b4.x, b4.y, b4.z, b4.w};
#pragma unroll
            for (int i = 0; i < 4; i++)
#pragma unroll
                for (int j = 0; j < 4; j++) c[i][j] += av[i] * bv[j];
        }
        __syncthreads();
    }
#pragma unroll
    for (int i = 0; i < 4; i++) {
        int r = row0 + ty * 4 + i;
        if (r >= M) continue;
#pragma unroll
        for (int j = 0; j < 4; j++) {
            int col = col0 + tx * 4 + j;
            if (col < N) {
                float v = c[i][j] + bias[col];
                if (doRelu) v = fmaxf(v, 0.f);
                C[(size_t)r * N + col] = v;
            }
        }
    }
}

// ---------------- 4. transpose mol ----------------
__global__ void transpose_mol(const float* __restrict__ mol, float* __restrict__ molT) {
    int idx = blockIdx.x * 256 + threadIdx.x;
    if (idx < Bn * En) {
        int b = idx / En, e = idx % En;
        molT[(size_t)e * Bn + b] = mol[idx];
    }
}

// ---------------- 5. attention logits + row softmax ----------------
// block b (256 threads): logit_j = q[b,:] . mol[j,:], softmax over j.
__global__ void attn_kernel(const float* __restrict__ q, const float* __restrict__ molT,
                            float* __restrict__ attn, float* __restrict__ attnT) {
    int b = blockIdx.x;
    int j = threadIdx.x;
    __shared__ float qs[En];
    for (int e = j; e < En; e += 256) qs[e] = q[(size_t)b * En + e];
    __syncthreads();
    float acc = 0.f;
#pragma unroll 4
    for (int k = 0; k < En; k++) acc += qs[k] * molT[(size_t)k * Bn + j];
    float m = blockReduceMax(acc);
    float e = __expf(acc - m);
    float s = blockReduceSum(e);
    float a = e / s;
    attn[(size_t)b * Bn + j] = a;
    attnT[(size_t)j * Bn + b] = a;
}

// ---------------- 6. fused_x1 = softmax(attn @ mol, axis=1) ----------------
// 4 batch rows per block, 320 threads (cols 0..299 active for output).
__global__ void fuse1_kernel(const float* __restrict__ attn, const float* __restrict__ mol,
                             float* __restrict__ fx1) {
    int b0 = blockIdx.x * 4;
    int t = threadIdx.x;
    __shared__ float as[4][Bn];
    for (int i = t; i < 4 * Bn; i += 320)
        as[i >> 8][i & 255] = attn[(size_t)(b0 + (i >> 8)) * Bn + (i & 255)];
    __syncthreads();
    float acc[4] = {0.f, 0.f, 0.f, 0.f};
    if (t < En) {
        for (int j = 0; j < Bn; j++) {
            float v = mol[(size_t)j * En + t];
#pragma unroll
            for (int i = 0; i < 4; i++) acc[i] += as[i][j] * v;
        }
    }
#pragma unroll
    for (int i = 0; i < 4; i++) {
        float val = (t < En) ? acc[i] : -FLT_MAX;
        float m = blockReduceMax(val);
        float e = (t < En) ? __expf(acc[i] - m) : 0.f;
        float s = blockReduceSum(e);
        if (t < En) fx1[(size_t)(b0 + i) * En + t] = e / s;
    }
}

// ---------------- 7. fused_x2 = softmax(attn^T @ x1, axis=1) ----------------
// 4 batch rows per block, 320 threads, one float4 column per thread.
__global__ void fuse2_kernel(const float* __restrict__ attnT, const float* __restrict__ x1,
                             float* __restrict__ fx2) {
    int b0 = blockIdx.x * 4;
    int t = threadIdx.x;   // 0..319
    __shared__ float as[4][Bn];
    for (int i = t; i < 4 * Bn; i += 320)
        as[i >> 8][i & 255] = attnT[(size_t)(b0 + (i >> 8)) * Bn + (i & 255)];
    __syncthreads();
    float4 acc[4];
#pragma unroll
    for (int i = 0; i < 4; i++) acc[i] = make_float4(0.f, 0.f, 0.f, 0.f);
    const float4* x1v = (const float4*)x1;
    for (int j = 0; j < Bn; j++) {
        float4 v = x1v[(size_t)j * D4 + t];
#pragma unroll
        for (int i = 0; i < 4; i++) {
            float a = as[i][j];
            acc[i].x += a * v.x; acc[i].y += a * v.y;
            acc[i].z += a * v.z; acc[i].w += a * v.w;
        }
    }
#pragma unroll
    for (int i = 0; i < 4; i++) {
        float m = fmaxf(fmaxf(acc[i].x, acc[i].y), fmaxf(acc[i].z, acc[i].w));
        m = blockReduceMax(m);
        float ex = __expf(acc[i].x - m), ey = __expf(acc[i].y - m);
        float ez = __expf(acc[i].z - m), ew = __expf(acc[i].w - m);
        float s = blockReduceSum((ex + ey) + (ez + ew));
        float inv = 1.f / s;
        ((float4*)fx2)[(size_t)(b0 + i) * D4 + t] =
            make_float4(ex * inv, ey * inv, ez * inv, ew * inv);
    }
}

// ---------------- 8. combined -> fc1(relu) -> fc2 ----------------
// 4 batch rows per block, 256 threads; thread t owns hidden unit t.
__global__ void final_kernel(const float* __restrict__ x1, const float* __restrict__ fx2,
                             const float* __restrict__ mol, const float* __restrict__ fx1,
                             const float* __restrict__ Wf1, const float* __restrict__ bf1,
                             const float* __restrict__ Wf2, const float* __restrict__ bf2,
                             float* __restrict__ out) {
    int b0 = blockIdx.x * 4;
    int t = threadIdx.x;   // 0..255
    __shared__ float comb[4][DE];
    for (int idx = t; idx < 4 * DE; idx += 256) {
        int i = idx / DE, k = idx % DE;
        int b = b0 + i;
        float v;
        if (k < Dn) v = x1[(size_t)b * Dn + k] * (fx2[(size_t)b * Dn + k] + 1.f);
        else {
            int e = k - Dn;
            v = mol[(size_t)b * En + e] * (fx1[(size_t)b * En + e] + 1.f);
        }
        comb[i][k] = v;
    }
    __syncthreads();
    float acc[4] = {0.f, 0.f, 0.f, 0.f};
    for (int k = 0; k < DE; k++) {
        float w = Wf1[(size_t)k * Hn + t];
#pragma unroll
        for (int i = 0; i < 4; i++) acc[i] += w * comb[i][k];
    }
    float bb = bf1[t];
    float w2 = Wf2[t];
#pragma unroll
    for (int i = 0; i < 4; i++) {
        float h = fmaxf(acc[i] + bb, 0.f);
        float s = blockReduceSum(h * w2);
        if (t == 0) out[b0 + i] = s + bf2[0];
    }
}

// ---------------- launch ----------------
extern "C" void kernel_launch(void* const* d_in, const int* in_sizes, int n_in,
                              void* d_out, int out_size) {
    const float* tok  = (const float*)d_in[0];
    const int*   lens = (const int*)  d_in[1];
    const float* mol  = (const float*)d_in[2];
    const float* Wp   = (const float*)d_in[3];
    const float* bp   = (const float*)d_in[4];
    const float* Wa   = (const float*)d_in[5];
    const float* ba   = (const float*)d_in[6];
    const float* Wf1  = (const float*)d_in[7];
    const float* bf1  = (const float*)d_in[8];
    const float* Wf2  = (const float*)d_in[9];
    const float* bf2  = (const float*)d_in[10];
    float* out = (float*)d_out;

    void *p_pooled, *p_x1, *p_q, *p_molT, *p_attn, *p_attnT, *p_fx1, *p_fx2;
    cudaGetSymbolAddress(&p_pooled, g_pooled);
    cudaGetSymbolAddress(&p_x1, g_x1);
    cudaGetSymbolAddress(&p_q, g_q);
    cudaGetSymbolAddress(&p_molT, g_molT);
    cudaGetSymbolAddress(&p_attn, g_attn);
    cudaGetSymbolAddress(&p_attnT, g_attnT);
    cudaGetSymbolAddress(&p_fx1, g_fx1);
    cudaGetSymbolAddress(&p_fx2, g_fx2);

    float* pooled = (float*)p_pooled;
    float* x1     = (float*)p_x1;
    float* q      = (float*)p_q;
    float* molT   = (float*)p_molT;
    float* attn   = (float*)p_attn;
    float* attnT  = (float*)p_attnT;
    float* fx1    = (float*)p_fx1;
    float* fx2    = (float*)p_fx2;

    pool_kernel<<<dim3(Bn, 2), 160>>>(tok, lens, pooled);
    gemm_bias_act<<<dim3(Dn / 64, Bn / 64), 256>>>(pooled, Wp, bp, x1, Bn, Dn, Dn, 1);
    gemm_bias_act<<<dim3((En + 63) / 64, Bn / 64), 256>>>(x1, Wa, ba, q, Bn, En, Dn, 0);
    transpose_mol<<<(Bn * En + 255) / 256, 256>>>(mol, molT);
    attn_kernel<<<Bn, 256>>>(q, molT, attn, attnT);
    fuse1_kernel<<<Bn / 4, 320>>>(attn, mol, fx1);
    fuse2_kernel<<<Bn / 4, 320>>>(attnT, x1, fx2);
    final_kernel<<<Bn / 4, 256>>>(x1, fx2, mol, fx1, Wf1, bf1, Wf2, bf2, out);
}